// round 5
// baseline (speedup 1.0000x reference)
#include <cuda_runtime.h>
#include <cuda_bf16.h>

#define KC 16
#define DD 16
#define NQUAD 136          // i<=j pairs
#define NFEAT 152          // 136 quad + 16 linear

// Coefficients: [feature][cluster], cluster-contiguous. 64B per feature,
// 64B-aligned so each feature block is one pair of 256-bit loads.
__device__ __align__(64) float g_coef[NFEAT * KC];
__device__ __align__(16) float g_const[KC];

// ---------------------------------------------------------------------------
// f32x2 packed helpers
// ---------------------------------------------------------------------------
__device__ __forceinline__ unsigned long long f2dup(float v) {
    unsigned long long r;
    asm("mov.b64 %0, {%1, %1};" : "=l"(r) : "f"(v));
    return r;
}
__device__ __forceinline__ unsigned long long f2mul(unsigned long long a, unsigned long long b) {
    unsigned long long r;
    asm("mul.rn.f32x2 %0, %1, %2;" : "=l"(r) : "l"(a), "l"(b));
    return r;
}
__device__ __forceinline__ unsigned long long f2fma(unsigned long long a, unsigned long long b,
                                                    unsigned long long c) {
    unsigned long long r;
    asm("fma.rn.f32x2 %0, %1, %2, %3;" : "=l"(r) : "l"(a), "l"(b), "l"(c));
    return r;
}
__device__ __forceinline__ void f2unpack(unsigned long long v, float& lo, float& hi) {
    asm("mov.b64 {%0, %1}, %2;" : "=f"(lo), "=f"(hi) : "l"(v));
}
// 256-bit read-only global load (sm_100+): 4 x u64 = 8 clusters' coefficients
__device__ __forceinline__ void ldg256(const float* p,
                                       unsigned long long& a, unsigned long long& b,
                                       unsigned long long& c, unsigned long long& d) {
    asm("ld.global.nc.v4.u64 {%0, %1, %2, %3}, [%4];"
        : "=l"(a), "=l"(b), "=l"(c), "=l"(d) : "l"(p));
}
__device__ __forceinline__ unsigned long long ldg64(const float* p) {
    unsigned long long r;
    asm("ld.global.nc.u64 %0, [%1];" : "=l"(r) : "l"(p));
    return r;
}

// ---------------------------------------------------------------------------
// Precompute: one warp per cluster; Gauss-Jordan inverse, logdet, b = P*mu.
// ---------------------------------------------------------------------------
__global__ void gmm_precompute(const float* __restrict__ pi,
                               const float* __restrict__ mu,
                               const float* __restrict__ Sigma) {
    const int w    = threadIdx.x >> 5;
    const int lane = threadIdx.x & 31;
    const int j    = lane & 15;

    float a[16], inv[16];
#pragma unroll
    for (int i = 0; i < 16; ++i) {
        a[i]   = Sigma[w * 256 + i * 16 + j];
        inv[i] = (i == j) ? 1.0f : 0.0f;
    }

    float logdet = 0.0f;
#pragma unroll
    for (int k = 0; k < 16; ++k) {
        float piv = __shfl_sync(0xffffffffu, a[k], k);
        logdet += logf(piv);
        float ip = 1.0f / piv;
        a[k]   *= ip;
        inv[k] *= ip;
#pragma unroll
        for (int i = 0; i < 16; ++i) {
            if (i != k) {
                float m = __shfl_sync(0xffffffffu, a[i], k);
                a[i]   = fmaf(-m, a[k],   a[i]);
                inv[i] = fmaf(-m, inv[k], inv[i]);
            }
        }
    }

    const float mu_j = mu[w * 16 + j];
    float bv[16];
#pragma unroll
    for (int i = 0; i < 16; ++i) {
        float v = inv[i] * mu_j;
        v += __shfl_xor_sync(0xffffffffu, v, 8);
        v += __shfl_xor_sync(0xffffffffu, v, 4);
        v += __shfl_xor_sync(0xffffffffu, v, 2);
        v += __shfl_xor_sync(0xffffffffu, v, 1);
        bv[i] = v;
    }
    float muPmu = 0.0f;
#pragma unroll
    for (int i = 0; i < 16; ++i) muPmu += bv[i] * mu[w * 16 + i];

    if (lane < 16) {
#pragma unroll
        for (int i = 0; i < 16; ++i) {
            if (i <= j) {
                float c = (i == j ? -0.5f : -1.0f) * inv[i];
                g_coef[(j * (j + 1) / 2 + i) * KC + w] = c;
            }
        }
    }
    if (lane == 0) {
#pragma unroll
        for (int i = 0; i < 16; ++i) g_coef[(NQUAD + i) * KC + w] = bv[i];
        g_const[w] = logf(pi[w]) - 0.5f * logdet - 8.0f * 1.8378770664093453f - 0.5f * muPmu;
    }
}

// ---------------------------------------------------------------------------
// softmax + float4 store for one point's 16 logits
// ---------------------------------------------------------------------------
__device__ __forceinline__ void softmax_store(const float* l, float* outp) {
    float mx = l[0];
#pragma unroll
    for (int k = 1; k < 16; ++k) mx = fmaxf(mx, l[k]);
    float e[16], s = 0.0f;
#pragma unroll
    for (int k = 0; k < 16; ++k) { e[k] = __expf(l[k] - mx); s += e[k]; }
    float r = __fdividef(1.0f, s);
    float4* o = reinterpret_cast<float4*>(outp);
    o[0] = make_float4(e[0] * r,  e[1] * r,  e[2] * r,  e[3] * r);
    o[1] = make_float4(e[4] * r,  e[5] * r,  e[6] * r,  e[7] * r);
    o[2] = make_float4(e[8] * r,  e[9] * r,  e[10] * r, e[11] * r);
    o[3] = make_float4(e[12] * r, e[13] * r, e[14] * r, e[15] * r);
}

// ---------------------------------------------------------------------------
// Main kernel: 2 points/thread, duplicated-X f32x2, cluster-packed acc.
// Coefficients read straight from L1-resident global via 256-bit LDG —
// NO shared memory in the hot loop (the smem crossbar was the R2/R4 binder:
// 4 LDS.128/feature x 4cyc effective = 16 cyc/feature > 8 FMA cyc/feature).
// Per feature: 2 LDG.256 + 2 f2mul + 16 f2fma.
// ---------------------------------------------------------------------------
__global__ void __launch_bounds__(256) gmm_main(const float* __restrict__ x,
                                                float* __restrict__ out, int n) {
    long long t  = (long long)blockIdx.x * blockDim.x + threadIdx.x;
    long long n0 = 2 * t;
    if (n0 >= n) return;
    const bool hasB = (n0 + 1 < n);

    const float4* xA = reinterpret_cast<const float4*>(x + n0 * DD);
    const float4* xB = reinterpret_cast<const float4*>(x + (hasB ? (n0 + 1) : n0) * DD);

    // duplicated X: XA[i] = (xA_i, xA_i)
    unsigned long long XA[16], XB[16];
#pragma unroll
    for (int q = 0; q < 4; ++q) {
        float4 va = xA[q], vb = xB[q];
        XA[4 * q + 0] = f2dup(va.x); XA[4 * q + 1] = f2dup(va.y);
        XA[4 * q + 2] = f2dup(va.z); XA[4 * q + 3] = f2dup(va.w);
        XB[4 * q + 0] = f2dup(vb.x); XB[4 * q + 1] = f2dup(vb.y);
        XB[4 * q + 2] = f2dup(vb.z); XB[4 * q + 3] = f2dup(vb.w);
    }

    // acc[m] = clusters (2m, 2m+1) packed; init from constants (plain pairs)
    unsigned long long accA[8], accB[8];
#pragma unroll
    for (int m = 0; m < 8; ++m) {
        unsigned long long c = ldg64(g_const + 2 * m);
        accA[m] = c; accB[m] = c;
    }

    // quadratic features (i<=j), feature p = j*(j+1)/2 + i
    int p = 0;
#pragma unroll
    for (int j = 0; j < 16; ++j) {
#pragma unroll
        for (int i = 0; i <= j; ++i) {
            unsigned long long fA = f2mul(XA[i], XA[j]);
            unsigned long long fB = f2mul(XB[i], XB[j]);
            const float* cf = g_coef + p * KC;
            unsigned long long c0, c1, c2, c3, c4, c5, c6, c7;
            ldg256(cf,     c0, c1, c2, c3);   // clusters 0..7
            ldg256(cf + 8, c4, c5, c6, c7);   // clusters 8..15
            accA[0] = f2fma(c0, fA, accA[0]); accB[0] = f2fma(c0, fB, accB[0]);
            accA[1] = f2fma(c1, fA, accA[1]); accB[1] = f2fma(c1, fB, accB[1]);
            accA[2] = f2fma(c2, fA, accA[2]); accB[2] = f2fma(c2, fB, accB[2]);
            accA[3] = f2fma(c3, fA, accA[3]); accB[3] = f2fma(c3, fB, accB[3]);
            accA[4] = f2fma(c4, fA, accA[4]); accB[4] = f2fma(c4, fB, accB[4]);
            accA[5] = f2fma(c5, fA, accA[5]); accB[5] = f2fma(c5, fB, accB[5]);
            accA[6] = f2fma(c6, fA, accA[6]); accB[6] = f2fma(c6, fB, accB[6]);
            accA[7] = f2fma(c7, fA, accA[7]); accB[7] = f2fma(c7, fB, accB[7]);
            ++p;
        }
    }
    // linear features (X already duplicated)
#pragma unroll
    for (int i = 0; i < 16; ++i) {
        const float* cf = g_coef + (NQUAD + i) * KC;
        unsigned long long c0, c1, c2, c3, c4, c5, c6, c7;
        ldg256(cf,     c0, c1, c2, c3);
        ldg256(cf + 8, c4, c5, c6, c7);
        accA[0] = f2fma(c0, XA[i], accA[0]); accB[0] = f2fma(c0, XB[i], accB[0]);
        accA[1] = f2fma(c1, XA[i], accA[1]); accB[1] = f2fma(c1, XB[i], accB[1]);
        accA[2] = f2fma(c2, XA[i], accA[2]); accB[2] = f2fma(c2, XB[i], accB[2]);
        accA[3] = f2fma(c3, XA[i], accA[3]); accB[3] = f2fma(c3, XB[i], accB[3]);
        accA[4] = f2fma(c4, XA[i], accA[4]); accB[4] = f2fma(c4, XB[i], accB[4]);
        accA[5] = f2fma(c5, XA[i], accA[5]); accB[5] = f2fma(c5, XB[i], accB[5]);
        accA[6] = f2fma(c6, XA[i], accA[6]); accB[6] = f2fma(c6, XB[i], accB[6]);
        accA[7] = f2fma(c7, XA[i], accA[7]); accB[7] = f2fma(c7, XB[i], accB[7]);
    }

    // unpack logits
    float la[16], lb[16];
#pragma unroll
    for (int m = 0; m < 8; ++m) {
        f2unpack(accA[m], la[2 * m], la[2 * m + 1]);
        f2unpack(accB[m], lb[2 * m], lb[2 * m + 1]);
    }

    softmax_store(la, out + n0 * KC);
    if (hasB) softmax_store(lb, out + (n0 + 1) * KC);
}

extern "C" void kernel_launch(void* const* d_in, const int* in_sizes, int n_in,
                              void* d_out, int out_size) {
    const float* x     = (const float*)d_in[0];
    const float* pi    = (const float*)d_in[1];
    const float* mu    = (const float*)d_in[2];
    const float* Sigma = (const float*)d_in[3];
    float* out = (float*)d_out;

    int n = in_sizes[0] / DD;

    gmm_precompute<<<1, 512>>>(pi, mu, Sigma);

    int nthreads = (n + 1) / 2;   // 2 points per thread
    int block = 256;
    int grid  = (nthreads + block - 1) / block;
    gmm_main<<<grid, block>>>(x, out, n);
}

// round 6
// speedup vs baseline: 1.4279x; 1.4279x over previous
#include <cuda_runtime.h>
#include <cuda_bf16.h>

#define KC 16
#define DD 16
#define NQUAD 136          // i<=j pairs
#define NFEAT 152          // 136 quad + 16 linear

__device__ float g_coef[NFEAT * KC];   // [feature][cluster]
__device__ float g_const[KC];

// ---------------------------------------------------------------------------
// f32x2 packed helpers
// ---------------------------------------------------------------------------
__device__ __forceinline__ unsigned long long f2dup(float v) {
    unsigned long long r;
    asm("mov.b64 %0, {%1, %1};" : "=l"(r) : "f"(v));
    return r;
}
__device__ __forceinline__ unsigned long long f2mul(unsigned long long a, unsigned long long b) {
    unsigned long long r;
    asm("mul.rn.f32x2 %0, %1, %2;" : "=l"(r) : "l"(a), "l"(b));
    return r;
}
__device__ __forceinline__ unsigned long long f2fma(unsigned long long a, unsigned long long b,
                                                    unsigned long long c) {
    unsigned long long r;
    asm("fma.rn.f32x2 %0, %1, %2, %3;" : "=l"(r) : "l"(a), "l"(b), "l"(c));
    return r;
}
__device__ __forceinline__ void f2unpack(unsigned long long v, float& lo, float& hi) {
    asm("mov.b64 {%0, %1}, %2;" : "=f"(lo), "=f"(hi) : "l"(v));
}

// ---------------------------------------------------------------------------
// Software exp: NO MUFU. 2^(x*log2e) with alu-pipe int ops + fma-pipe poly.
// x <= 0 on entry (post max-subtraction). Rel err ~3e-6.
// ---------------------------------------------------------------------------
__device__ __forceinline__ float fast_exp(float x) {
    x = fmaxf(x, -87.0f);                       // underflow clamp (FMNMX)
    float y = x * 1.4426950408889634f;          // FMUL
    int   ki = __float2int_rn(y);               // F2I (alu class)
    float kf = (float)ki;                       // I2F (alu class)
    float f  = y - kf;                          // FADD, f in [-0.5, 0.5]
    float p  = 1.3333558e-3f;                   // 2^f Taylor/minimax deg-5
    p = fmaf(p, f, 9.6181291e-3f);
    p = fmaf(p, f, 5.5504109e-2f);
    p = fmaf(p, f, 2.4022651e-1f);
    p = fmaf(p, f, 6.9314718e-1f);
    p = fmaf(p, f, 1.0f);
    float s = __int_as_float((ki + 127) << 23); // IADD + SHL (alu)
    return p * s;                               // FMUL
}

// ---------------------------------------------------------------------------
// Precompute: one warp per cluster; Gauss-Jordan inverse, logdet, b = P*mu.
// ---------------------------------------------------------------------------
__global__ void gmm_precompute(const float* __restrict__ pi,
                               const float* __restrict__ mu,
                               const float* __restrict__ Sigma) {
    const int w    = threadIdx.x >> 5;
    const int lane = threadIdx.x & 31;
    const int j    = lane & 15;

    float a[16], inv[16];
#pragma unroll
    for (int i = 0; i < 16; ++i) {
        a[i]   = Sigma[w * 256 + i * 16 + j];
        inv[i] = (i == j) ? 1.0f : 0.0f;
    }

    float logdet = 0.0f;
#pragma unroll
    for (int k = 0; k < 16; ++k) {
        float piv = __shfl_sync(0xffffffffu, a[k], k);
        logdet += logf(piv);
        float ip = 1.0f / piv;
        a[k]   *= ip;
        inv[k] *= ip;
#pragma unroll
        for (int i = 0; i < 16; ++i) {
            if (i != k) {
                float m = __shfl_sync(0xffffffffu, a[i], k);
                a[i]   = fmaf(-m, a[k],   a[i]);
                inv[i] = fmaf(-m, inv[k], inv[i]);
            }
        }
    }

    const float mu_j = mu[w * 16 + j];
    float bv[16];
#pragma unroll
    for (int i = 0; i < 16; ++i) {
        float v = inv[i] * mu_j;
        v += __shfl_xor_sync(0xffffffffu, v, 8);
        v += __shfl_xor_sync(0xffffffffu, v, 4);
        v += __shfl_xor_sync(0xffffffffu, v, 2);
        v += __shfl_xor_sync(0xffffffffu, v, 1);
        bv[i] = v;
    }
    float muPmu = 0.0f;
#pragma unroll
    for (int i = 0; i < 16; ++i) muPmu += bv[i] * mu[w * 16 + i];

    if (lane < 16) {
#pragma unroll
        for (int i = 0; i < 16; ++i) {
            if (i <= j) {
                float c = (i == j ? -0.5f : -1.0f) * inv[i];
                g_coef[(j * (j + 1) / 2 + i) * KC + w] = c;
            }
        }
    }
    if (lane == 0) {
#pragma unroll
        for (int i = 0; i < 16; ++i) g_coef[(NQUAD + i) * KC + w] = bv[i];
        g_const[w] = logf(pi[w]) - 0.5f * logdet - 8.0f * 1.8378770664093453f - 0.5f * muPmu;
    }
}

// ---------------------------------------------------------------------------
// softmax + float4 store for one point's 16 logits (MUFU-free exp)
// ---------------------------------------------------------------------------
__device__ __forceinline__ void softmax_store(const float* l, float* outp) {
    float mx = l[0];
#pragma unroll
    for (int k = 1; k < 16; ++k) mx = fmaxf(mx, l[k]);
    float e[16], s = 0.0f;
#pragma unroll
    for (int k = 0; k < 16; ++k) { e[k] = fast_exp(l[k] - mx); s += e[k]; }
    float r = __fdividef(1.0f, s);   // single MUFU.RCP per point
    float4* o = reinterpret_cast<float4*>(outp);
    o[0] = make_float4(e[0] * r,  e[1] * r,  e[2] * r,  e[3] * r);
    o[1] = make_float4(e[4] * r,  e[5] * r,  e[6] * r,  e[7] * r);
    o[2] = make_float4(e[8] * r,  e[9] * r,  e[10] * r, e[11] * r);
    o[3] = make_float4(e[12] * r, e[13] * r, e[14] * r, e[15] * r);
}

// ---------------------------------------------------------------------------
// Main kernel: identical structure to the R2 best (2 pts/thread, duplicated-X
// f32x2, cluster-packed acc, plain-float smem coefficients, 4 LDS.128/feature)
// with MUFU-free softmax.
// ---------------------------------------------------------------------------
__global__ void __launch_bounds__(256) gmm_main(const float* __restrict__ x,
                                                float* __restrict__ out, int n) {
    __shared__ __align__(16) float s_coef[NFEAT * KC];   // [feature][cluster]
    __shared__ __align__(16) float s_const[KC];

    for (int idx = threadIdx.x; idx < NFEAT * KC; idx += blockDim.x)
        s_coef[idx] = g_coef[idx];
    if (threadIdx.x < KC) s_const[threadIdx.x] = g_const[threadIdx.x];
    __syncthreads();

    long long t  = (long long)blockIdx.x * blockDim.x + threadIdx.x;
    long long n0 = 2 * t;
    if (n0 >= n) return;
    const bool hasB = (n0 + 1 < n);

    const float4* xA = reinterpret_cast<const float4*>(x + n0 * DD);
    const float4* xB = reinterpret_cast<const float4*>(x + (hasB ? (n0 + 1) : n0) * DD);

    unsigned long long XA[16], XB[16];
#pragma unroll
    for (int q = 0; q < 4; ++q) {
        float4 va = xA[q], vb = xB[q];
        XA[4 * q + 0] = f2dup(va.x); XA[4 * q + 1] = f2dup(va.y);
        XA[4 * q + 2] = f2dup(va.z); XA[4 * q + 3] = f2dup(va.w);
        XB[4 * q + 0] = f2dup(vb.x); XB[4 * q + 1] = f2dup(vb.y);
        XB[4 * q + 2] = f2dup(vb.z); XB[4 * q + 3] = f2dup(vb.w);
    }

    unsigned long long accA[8], accB[8];
    {
        const unsigned long long* cu = reinterpret_cast<const unsigned long long*>(s_const);
#pragma unroll
        for (int m = 0; m < 8; ++m) { accA[m] = cu[m]; accB[m] = cu[m]; }
    }

    // quadratic features (i<=j), feature p = j*(j+1)/2 + i
    int p = 0;
#pragma unroll
    for (int j = 0; j < 16; ++j) {
#pragma unroll
        for (int i = 0; i <= j; ++i) {
            unsigned long long fA = f2mul(XA[i], XA[j]);
            unsigned long long fB = f2mul(XB[i], XB[j]);
            const ulonglong2* cp = reinterpret_cast<const ulonglong2*>(s_coef + p * KC);
#pragma unroll
            for (int m = 0; m < 4; ++m) {
                ulonglong2 cc = cp[m];             // clusters 4m..4m+3
                accA[2 * m]     = f2fma(cc.x, fA, accA[2 * m]);
                accA[2 * m + 1] = f2fma(cc.y, fA, accA[2 * m + 1]);
                accB[2 * m]     = f2fma(cc.x, fB, accB[2 * m]);
                accB[2 * m + 1] = f2fma(cc.y, fB, accB[2 * m + 1]);
            }
            ++p;
        }
    }
    // linear features (X already duplicated)
#pragma unroll
    for (int i = 0; i < 16; ++i) {
        const ulonglong2* cp = reinterpret_cast<const ulonglong2*>(s_coef + (NQUAD + i) * KC);
#pragma unroll
        for (int m = 0; m < 4; ++m) {
            ulonglong2 cc = cp[m];
            accA[2 * m]     = f2fma(cc.x, XA[i], accA[2 * m]);
            accA[2 * m + 1] = f2fma(cc.y, XA[i], accA[2 * m + 1]);
            accB[2 * m]     = f2fma(cc.x, XB[i], accB[2 * m]);
            accB[2 * m + 1] = f2fma(cc.y, XB[i], accB[2 * m + 1]);
        }
    }

    // unpack logits
    float la[16], lb[16];
#pragma unroll
    for (int m = 0; m < 8; ++m) {
        f2unpack(accA[m], la[2 * m], la[2 * m + 1]);
        f2unpack(accB[m], lb[2 * m], lb[2 * m + 1]);
    }

    softmax_store(la, out + n0 * KC);
    if (hasB) softmax_store(lb, out + (n0 + 1) * KC);
}

extern "C" void kernel_launch(void* const* d_in, const int* in_sizes, int n_in,
                              void* d_out, int out_size) {
    const float* x     = (const float*)d_in[0];
    const float* pi    = (const float*)d_in[1];
    const float* mu    = (const float*)d_in[2];
    const float* Sigma = (const float*)d_in[3];
    float* out = (float*)d_out;

    int n = in_sizes[0] / DD;

    gmm_precompute<<<1, 512>>>(pi, mu, Sigma);

    int nthreads = (n + 1) / 2;   // 2 points per thread
    int block = 256;
    int grid  = (nthreads + block - 1) / block;
    gmm_main<<<grid, block>>>(x, out, n);
}

// round 7
// speedup vs baseline: 1.7022x; 1.1921x over previous
#include <cuda_runtime.h>
#include <cuda_bf16.h>

#define KC 16
#define DD 16
#define NQUAD 136          // i<=j pairs
#define NFEAT 152          // 136 quad + 16 linear

// Staging area written by the precompute kernel...
__device__ float g_coef[NFEAT * KC];   // [feature][cluster]
__device__ float g_const[KC];
// ...then copied into constant banks (uniform-datapath loads in the hot loop).
__constant__ __align__(16) float c_coef[NFEAT * KC];
__constant__ __align__(16) float c_const[KC];

// ---------------------------------------------------------------------------
// f32x2 packed helpers
// ---------------------------------------------------------------------------
__device__ __forceinline__ unsigned long long f2dup(float v) {
    unsigned long long r;
    asm("mov.b64 %0, {%1, %1};" : "=l"(r) : "f"(v));
    return r;
}
__device__ __forceinline__ unsigned long long f2mul(unsigned long long a, unsigned long long b) {
    unsigned long long r;
    asm("mul.rn.f32x2 %0, %1, %2;" : "=l"(r) : "l"(a), "l"(b));
    return r;
}
__device__ __forceinline__ unsigned long long f2fma(unsigned long long a, unsigned long long b,
                                                    unsigned long long c) {
    unsigned long long r;
    asm("fma.rn.f32x2 %0, %1, %2, %3;" : "=l"(r) : "l"(a), "l"(b), "l"(c));
    return r;
}
__device__ __forceinline__ void f2unpack(unsigned long long v, float& lo, float& hi) {
    asm("mov.b64 {%0, %1}, %2;" : "=f"(lo), "=f"(hi) : "l"(v));
}

// ---------------------------------------------------------------------------
// Software exp: no MUFU except 1 RCP/pt downstream. Rel err ~3e-6.
// ---------------------------------------------------------------------------
__device__ __forceinline__ float fast_exp(float x) {
    x = fmaxf(x, -87.0f);
    float y = x * 1.4426950408889634f;
    int   ki = __float2int_rn(y);
    float kf = (float)ki;
    float f  = y - kf;
    float p  = 1.3333558e-3f;
    p = fmaf(p, f, 9.6181291e-3f);
    p = fmaf(p, f, 5.5504109e-2f);
    p = fmaf(p, f, 2.4022651e-1f);
    p = fmaf(p, f, 6.9314718e-1f);
    p = fmaf(p, f, 1.0f);
    float s = __int_as_float((ki + 127) << 23);
    return p * s;
}

// ---------------------------------------------------------------------------
// Precompute: one warp per cluster; Gauss-Jordan inverse, logdet, b = P*mu.
// ---------------------------------------------------------------------------
__global__ void gmm_precompute(const float* __restrict__ pi,
                               const float* __restrict__ mu,
                               const float* __restrict__ Sigma) {
    const int w    = threadIdx.x >> 5;
    const int lane = threadIdx.x & 31;
    const int j    = lane & 15;

    float a[16], inv[16];
#pragma unroll
    for (int i = 0; i < 16; ++i) {
        a[i]   = Sigma[w * 256 + i * 16 + j];
        inv[i] = (i == j) ? 1.0f : 0.0f;
    }

    float logdet = 0.0f;
#pragma unroll
    for (int k = 0; k < 16; ++k) {
        float piv = __shfl_sync(0xffffffffu, a[k], k);
        logdet += logf(piv);
        float ip = 1.0f / piv;
        a[k]   *= ip;
        inv[k] *= ip;
#pragma unroll
        for (int i = 0; i < 16; ++i) {
            if (i != k) {
                float m = __shfl_sync(0xffffffffu, a[i], k);
                a[i]   = fmaf(-m, a[k],   a[i]);
                inv[i] = fmaf(-m, inv[k], inv[i]);
            }
        }
    }

    const float mu_j = mu[w * 16 + j];
    float bv[16];
#pragma unroll
    for (int i = 0; i < 16; ++i) {
        float v = inv[i] * mu_j;
        v += __shfl_xor_sync(0xffffffffu, v, 8);
        v += __shfl_xor_sync(0xffffffffu, v, 4);
        v += __shfl_xor_sync(0xffffffffu, v, 2);
        v += __shfl_xor_sync(0xffffffffu, v, 1);
        bv[i] = v;
    }
    float muPmu = 0.0f;
#pragma unroll
    for (int i = 0; i < 16; ++i) muPmu += bv[i] * mu[w * 16 + i];

    if (lane < 16) {
#pragma unroll
        for (int i = 0; i < 16; ++i) {
            if (i <= j) {
                float c = (i == j ? -0.5f : -1.0f) * inv[i];
                g_coef[(j * (j + 1) / 2 + i) * KC + w] = c;
            }
        }
    }
    if (lane == 0) {
#pragma unroll
        for (int i = 0; i < 16; ++i) g_coef[(NQUAD + i) * KC + w] = bv[i];
        g_const[w] = logf(pi[w]) - 0.5f * logdet - 8.0f * 1.8378770664093453f - 0.5f * muPmu;
    }
}

// ---------------------------------------------------------------------------
// softmax + float4 store for one point's 16 logits
// ---------------------------------------------------------------------------
__device__ __forceinline__ void softmax_store(const float* l, float* outp) {
    float mx = l[0];
#pragma unroll
    for (int k = 1; k < 16; ++k) mx = fmaxf(mx, l[k]);
    float e[16], s = 0.0f;
#pragma unroll
    for (int k = 0; k < 16; ++k) { e[k] = fast_exp(l[k] - mx); s += e[k]; }
    float r = __fdividef(1.0f, s);
    float4* o = reinterpret_cast<float4*>(outp);
    o[0] = make_float4(e[0] * r,  e[1] * r,  e[2] * r,  e[3] * r);
    o[1] = make_float4(e[4] * r,  e[5] * r,  e[6] * r,  e[7] * r);
    o[2] = make_float4(e[8] * r,  e[9] * r,  e[10] * r, e[11] * r);
    o[3] = make_float4(e[12] * r, e[13] * r, e[14] * r, e[15] * r);
}

// ---------------------------------------------------------------------------
// Main kernel: 2 pts/thread, duplicated-X f32x2, cluster-packed acc.
// Coefficients come from __constant__ at compile-time-immediate offsets ->
// LDCU into uniform registers (separate uniform port, floor 1/cyc) and FFMA
// with UR operands. Zero L1TEX traffic for coefficients: this removes the
// 512B-per-uniform-LDS.128 register-replication wall that pinned R2/R4/R6
// at ~65us. No shared memory at all.
// ---------------------------------------------------------------------------
__global__ void __launch_bounds__(256) gmm_main(const float* __restrict__ x,
                                                float* __restrict__ out, int n) {
    long long t  = (long long)blockIdx.x * blockDim.x + threadIdx.x;
    long long n0 = 2 * t;
    if (n0 >= n) return;
    const bool hasB = (n0 + 1 < n);

    const float4* xA = reinterpret_cast<const float4*>(x + n0 * DD);
    const float4* xB = reinterpret_cast<const float4*>(x + (hasB ? (n0 + 1) : n0) * DD);

    unsigned long long XA[16], XB[16];
#pragma unroll
    for (int q = 0; q < 4; ++q) {
        float4 va = xA[q], vb = xB[q];
        XA[4 * q + 0] = f2dup(va.x); XA[4 * q + 1] = f2dup(va.y);
        XA[4 * q + 2] = f2dup(va.z); XA[4 * q + 3] = f2dup(va.w);
        XB[4 * q + 0] = f2dup(vb.x); XB[4 * q + 1] = f2dup(vb.y);
        XB[4 * q + 2] = f2dup(vb.z); XB[4 * q + 3] = f2dup(vb.w);
    }

    const unsigned long long* ccoef  = reinterpret_cast<const unsigned long long*>(c_coef);
    const unsigned long long* cconst = reinterpret_cast<const unsigned long long*>(c_const);

    unsigned long long accA[8], accB[8];
#pragma unroll
    for (int m = 0; m < 8; ++m) {
        unsigned long long c = cconst[m];
        accA[m] = c; accB[m] = c;
    }

    // quadratic features (i<=j), feature p = j*(j+1)/2 + i
    int p = 0;
#pragma unroll
    for (int j = 0; j < 16; ++j) {
#pragma unroll
        for (int i = 0; i <= j; ++i) {
            unsigned long long fA = f2mul(XA[i], XA[j]);
            unsigned long long fB = f2mul(XB[i], XB[j]);
#pragma unroll
            for (int m = 0; m < 8; ++m) {
                unsigned long long cc = ccoef[p * 8 + m];   // clusters 2m,2m+1
                accA[m] = f2fma(cc, fA, accA[m]);
                accB[m] = f2fma(cc, fB, accB[m]);
            }
            ++p;
        }
    }
    // linear features (X already duplicated)
#pragma unroll
    for (int i = 0; i < 16; ++i) {
#pragma unroll
        for (int m = 0; m < 8; ++m) {
            unsigned long long cc = ccoef[(NQUAD + i) * 8 + m];
            accA[m] = f2fma(cc, XA[i], accA[m]);
            accB[m] = f2fma(cc, XB[i], accB[m]);
        }
    }

    // unpack logits
    float la[16], lb[16];
#pragma unroll
    for (int m = 0; m < 8; ++m) {
        f2unpack(accA[m], la[2 * m], la[2 * m + 1]);
        f2unpack(accB[m], lb[2 * m], lb[2 * m + 1]);
    }

    softmax_store(la, out + n0 * KC);
    if (hasB) softmax_store(lb, out + (n0 + 1) * KC);
}

extern "C" void kernel_launch(void* const* d_in, const int* in_sizes, int n_in,
                              void* d_out, int out_size) {
    const float* x     = (const float*)d_in[0];
    const float* pi    = (const float*)d_in[1];
    const float* mu    = (const float*)d_in[2];
    const float* Sigma = (const float*)d_in[3];
    float* out = (float*)d_out;

    int n = in_sizes[0] / DD;

    gmm_precompute<<<1, 512>>>(pi, mu, Sigma);

    // Copy computed coefficients into constant banks (D2D, graph-capturable).
    void* gcoef_addr  = nullptr;
    void* gconst_addr = nullptr;
    cudaGetSymbolAddress(&gcoef_addr,  g_coef);
    cudaGetSymbolAddress(&gconst_addr, g_const);
    cudaMemcpyToSymbolAsync(c_coef,  gcoef_addr,  sizeof(float) * NFEAT * KC, 0,
                            cudaMemcpyDeviceToDevice, 0);
    cudaMemcpyToSymbolAsync(c_const, gconst_addr, sizeof(float) * KC, 0,
                            cudaMemcpyDeviceToDevice, 0);

    int nthreads = (n + 1) / 2;   // 2 points per thread
    int block = 256;
    int grid  = (nthreads + block - 1) / block;
    gmm_main<<<grid, block>>>(x, out, n);
}

// round 8
// speedup vs baseline: 1.7394x; 1.0218x over previous
#include <cuda_runtime.h>
#include <cuda_bf16.h>

#define KC 16
#define DD 16
#define NQUAD 136          // i<=j pairs
#define NFEAT 152          // 136 quad + 16 linear
#define NALL  (NFEAT + 1)  // + constants row

// Staging area written by the precompute kernel (single symbol -> single copy).
// Layout: [feature][cluster] for features 0..151, row 152 = per-cluster consts.
__device__ float g_all[NALL * KC];
// Constant-bank mirror: hot loop reads via LDCU.128 into uniform registers.
__constant__ __align__(16) float c_all[NALL * KC];

// ---------------------------------------------------------------------------
// f32x2 packed helpers
// ---------------------------------------------------------------------------
__device__ __forceinline__ unsigned long long f2dup(float v) {
    unsigned long long r;
    asm("mov.b64 %0, {%1, %1};" : "=l"(r) : "f"(v));
    return r;
}
__device__ __forceinline__ unsigned long long f2mul(unsigned long long a, unsigned long long b) {
    unsigned long long r;
    asm("mul.rn.f32x2 %0, %1, %2;" : "=l"(r) : "l"(a), "l"(b));
    return r;
}
__device__ __forceinline__ unsigned long long f2fma(unsigned long long a, unsigned long long b,
                                                    unsigned long long c) {
    unsigned long long r;
    asm("fma.rn.f32x2 %0, %1, %2, %3;" : "=l"(r) : "l"(a), "l"(b), "l"(c));
    return r;
}
__device__ __forceinline__ void f2unpack(unsigned long long v, float& lo, float& hi) {
    asm("mov.b64 {%0, %1}, %2;" : "=f"(lo), "=f"(hi) : "l"(v));
}

// ---------------------------------------------------------------------------
// Software exp: FMA/ALU pipes only (1 MUFU.RCP per point downstream).
// ---------------------------------------------------------------------------
__device__ __forceinline__ float fast_exp(float x) {
    x = fmaxf(x, -87.0f);
    float y = x * 1.4426950408889634f;
    int   ki = __float2int_rn(y);
    float kf = (float)ki;
    float f  = y - kf;
    float p  = 1.3333558e-3f;
    p = fmaf(p, f, 9.6181291e-3f);
    p = fmaf(p, f, 5.5504109e-2f);
    p = fmaf(p, f, 2.4022651e-1f);
    p = fmaf(p, f, 6.9314718e-1f);
    p = fmaf(p, f, 1.0f);
    float s = __int_as_float((ki + 127) << 23);
    return p * s;
}

// ---------------------------------------------------------------------------
// Precompute: one warp per cluster; Gauss-Jordan inverse, logdet, b = P*mu.
// ---------------------------------------------------------------------------
__global__ void gmm_precompute(const float* __restrict__ pi,
                               const float* __restrict__ mu,
                               const float* __restrict__ Sigma) {
    const int w    = threadIdx.x >> 5;
    const int lane = threadIdx.x & 31;
    const int j    = lane & 15;

    float a[16], inv[16];
#pragma unroll
    for (int i = 0; i < 16; ++i) {
        a[i]   = Sigma[w * 256 + i * 16 + j];
        inv[i] = (i == j) ? 1.0f : 0.0f;
    }

    float logdet = 0.0f;
#pragma unroll
    for (int k = 0; k < 16; ++k) {
        float piv = __shfl_sync(0xffffffffu, a[k], k);
        logdet += logf(piv);
        float ip = 1.0f / piv;
        a[k]   *= ip;
        inv[k] *= ip;
#pragma unroll
        for (int i = 0; i < 16; ++i) {
            if (i != k) {
                float m = __shfl_sync(0xffffffffu, a[i], k);
                a[i]   = fmaf(-m, a[k],   a[i]);
                inv[i] = fmaf(-m, inv[k], inv[i]);
            }
        }
    }

    const float mu_j = mu[w * 16 + j];
    float bv[16];
#pragma unroll
    for (int i = 0; i < 16; ++i) {
        float v = inv[i] * mu_j;
        v += __shfl_xor_sync(0xffffffffu, v, 8);
        v += __shfl_xor_sync(0xffffffffu, v, 4);
        v += __shfl_xor_sync(0xffffffffu, v, 2);
        v += __shfl_xor_sync(0xffffffffu, v, 1);
        bv[i] = v;
    }
    float muPmu = 0.0f;
#pragma unroll
    for (int i = 0; i < 16; ++i) muPmu += bv[i] * mu[w * 16 + i];

    if (lane < 16) {
#pragma unroll
        for (int i = 0; i < 16; ++i) {
            if (i <= j) {
                float c = (i == j ? -0.5f : -1.0f) * inv[i];
                g_all[(j * (j + 1) / 2 + i) * KC + w] = c;
            }
        }
    }
    if (lane == 0) {
#pragma unroll
        for (int i = 0; i < 16; ++i) g_all[(NQUAD + i) * KC + w] = bv[i];
        g_all[NFEAT * KC + w] =
            logf(pi[w]) - 0.5f * logdet - 8.0f * 1.8378770664093453f - 0.5f * muPmu;
    }
}

// ---------------------------------------------------------------------------
// softmax + float4 store for one point's 16 logits
// ---------------------------------------------------------------------------
__device__ __forceinline__ void softmax_store(const float* l, float* outp) {
    float mx = l[0];
#pragma unroll
    for (int k = 1; k < 16; ++k) mx = fmaxf(mx, l[k]);
    float e[16], s = 0.0f;
#pragma unroll
    for (int k = 0; k < 16; ++k) { e[k] = fast_exp(l[k] - mx); s += e[k]; }
    float r = __fdividef(1.0f, s);
    float4* o = reinterpret_cast<float4*>(outp);
    o[0] = make_float4(e[0] * r,  e[1] * r,  e[2] * r,  e[3] * r);
    o[1] = make_float4(e[4] * r,  e[5] * r,  e[6] * r,  e[7] * r);
    o[2] = make_float4(e[8] * r,  e[9] * r,  e[10] * r, e[11] * r);
    o[3] = make_float4(e[12] * r, e[13] * r, e[14] * r, e[15] * r);
}

// ---------------------------------------------------------------------------
// Main kernel: 2 pts/thread, duplicated-X f32x2, cluster-packed acc,
// constant-bank coefficients read as ulonglong2 -> LDCU.128 (4 per feature,
// halving the uniform-port stream that co-bound the FMA pipe in R7).
// ---------------------------------------------------------------------------
__global__ void __launch_bounds__(256) gmm_main(const float* __restrict__ x,
                                                float* __restrict__ out, int n) {
    long long t  = (long long)blockIdx.x * blockDim.x + threadIdx.x;
    long long n0 = 2 * t;
    if (n0 >= n) return;
    const bool hasB = (n0 + 1 < n);

    const float4* xA = reinterpret_cast<const float4*>(x + n0 * DD);
    const float4* xB = reinterpret_cast<const float4*>(x + (hasB ? (n0 + 1) : n0) * DD);

    unsigned long long XA[16], XB[16];
#pragma unroll
    for (int q = 0; q < 4; ++q) {
        float4 va = xA[q], vb = xB[q];
        XA[4 * q + 0] = f2dup(va.x); XA[4 * q + 1] = f2dup(va.y);
        XA[4 * q + 2] = f2dup(va.z); XA[4 * q + 3] = f2dup(va.w);
        XB[4 * q + 0] = f2dup(vb.x); XB[4 * q + 1] = f2dup(vb.y);
        XB[4 * q + 2] = f2dup(vb.z); XB[4 * q + 3] = f2dup(vb.w);
    }

    // view constant bank as ulonglong2 rows: 4 x LDCU.128 per feature
    const ulonglong2* cvec = reinterpret_cast<const ulonglong2*>(c_all);

    unsigned long long accA[8], accB[8];
#pragma unroll
    for (int m = 0; m < 4; ++m) {
        ulonglong2 c = cvec[NFEAT * 4 + m];     // constants row
        accA[2 * m]     = c.x; accB[2 * m]     = c.x;
        accA[2 * m + 1] = c.y; accB[2 * m + 1] = c.y;
    }

    // quadratic features (i<=j), feature p = j*(j+1)/2 + i
    int p = 0;
#pragma unroll
    for (int j = 0; j < 16; ++j) {
#pragma unroll
        for (int i = 0; i <= j; ++i) {
            unsigned long long fA = f2mul(XA[i], XA[j]);
            unsigned long long fB = f2mul(XB[i], XB[j]);
#pragma unroll
            for (int m = 0; m < 4; ++m) {
                ulonglong2 cc = cvec[p * 4 + m];       // clusters 4m..4m+3
                accA[2 * m]     = f2fma(cc.x, fA, accA[2 * m]);
                accA[2 * m + 1] = f2fma(cc.y, fA, accA[2 * m + 1]);
                accB[2 * m]     = f2fma(cc.x, fB, accB[2 * m]);
                accB[2 * m + 1] = f2fma(cc.y, fB, accB[2 * m + 1]);
            }
            ++p;
        }
    }
    // linear features (X already duplicated)
#pragma unroll
    for (int i = 0; i < 16; ++i) {
#pragma unroll
        for (int m = 0; m < 4; ++m) {
            ulonglong2 cc = cvec[(NQUAD + i) * 4 + m];
            accA[2 * m]     = f2fma(cc.x, XA[i], accA[2 * m]);
            accA[2 * m + 1] = f2fma(cc.y, XA[i], accA[2 * m + 1]);
            accB[2 * m]     = f2fma(cc.x, XB[i], accB[2 * m]);
            accB[2 * m + 1] = f2fma(cc.y, XB[i], accB[2 * m + 1]);
        }
    }

    // unpack logits
    float la[16], lb[16];
#pragma unroll
    for (int m = 0; m < 8; ++m) {
        f2unpack(accA[m], la[2 * m], la[2 * m + 1]);
        f2unpack(accB[m], lb[2 * m], lb[2 * m + 1]);
    }

    softmax_store(la, out + n0 * KC);
    if (hasB) softmax_store(lb, out + (n0 + 1) * KC);
}

extern "C" void kernel_launch(void* const* d_in, const int* in_sizes, int n_in,
                              void* d_out, int out_size) {
    const float* x     = (const float*)d_in[0];
    const float* pi    = (const float*)d_in[1];
    const float* mu    = (const float*)d_in[2];
    const float* Sigma = (const float*)d_in[3];
    float* out = (float*)d_out;

    int n = in_sizes[0] / DD;

    gmm_precompute<<<1, 512>>>(pi, mu, Sigma);

    // Single D2D copy of all coefficients into the constant bank.
    void* gall_addr = nullptr;
    cudaGetSymbolAddress(&gall_addr, g_all);
    cudaMemcpyToSymbolAsync(c_all, gall_addr, sizeof(float) * NALL * KC, 0,
                            cudaMemcpyDeviceToDevice, 0);

    int nthreads = (n + 1) / 2;   // 2 points per thread
    int block = 256;
    int grid  = (nthreads + block - 1) / block;
    gmm_main<<<grid, block>>>(x, out, n);
}

// round 9
// speedup vs baseline: 1.8750x; 1.0780x over previous
#include <cuda_runtime.h>
#include <cuda_bf16.h>

#define KC 16
#define DD 16
#define NQUAD 136          // i<=j pairs
#define NFEAT 152          // 136 quad + 16 linear
#define NALL  (NFEAT + 1)  // + constants row

// Staging area written by the precompute kernel (single symbol -> single copy).
__device__ float g_all[NALL * KC];
// Constant-bank mirror: hot loop reads via uniform-path loads.
__constant__ __align__(16) float c_all[NALL * KC];

// ---------------------------------------------------------------------------
// f32x2 packed helpers
// ---------------------------------------------------------------------------
__device__ __forceinline__ unsigned long long f2dup(float v) {
    unsigned long long r;
    asm("mov.b64 %0, {%1, %1};" : "=l"(r) : "f"(v));
    return r;
}
__device__ __forceinline__ unsigned long long f2fma(unsigned long long a, unsigned long long b,
                                                    unsigned long long c) {
    unsigned long long r;
    asm("fma.rn.f32x2 %0, %1, %2, %3;" : "=l"(r) : "l"(a), "l"(b), "l"(c));
    return r;
}
__device__ __forceinline__ void f2unpack(unsigned long long v, float& lo, float& hi) {
    asm("mov.b64 {%0, %1}, %2;" : "=f"(lo), "=f"(hi) : "l"(v));
}

// ---------------------------------------------------------------------------
// Precompute: one warp per cluster; Gauss-Jordan inverse, logdet, b = P*mu.
// ---------------------------------------------------------------------------
__global__ void gmm_precompute(const float* __restrict__ pi,
                               const float* __restrict__ mu,
                               const float* __restrict__ Sigma) {
    const int w    = threadIdx.x >> 5;
    const int lane = threadIdx.x & 31;
    const int j    = lane & 15;

    float a[16], inv[16];
#pragma unroll
    for (int i = 0; i < 16; ++i) {
        a[i]   = Sigma[w * 256 + i * 16 + j];
        inv[i] = (i == j) ? 1.0f : 0.0f;
    }

    float logdet = 0.0f;
#pragma unroll
    for (int k = 0; k < 16; ++k) {
        float piv = __shfl_sync(0xffffffffu, a[k], k);
        logdet += logf(piv);
        float ip = 1.0f / piv;
        a[k]   *= ip;
        inv[k] *= ip;
#pragma unroll
        for (int i = 0; i < 16; ++i) {
            if (i != k) {
                float m = __shfl_sync(0xffffffffu, a[i], k);
                a[i]   = fmaf(-m, a[k],   a[i]);
                inv[i] = fmaf(-m, inv[k], inv[i]);
            }
        }
    }

    const float mu_j = mu[w * 16 + j];
    float bv[16];
#pragma unroll
    for (int i = 0; i < 16; ++i) {
        float v = inv[i] * mu_j;
        v += __shfl_xor_sync(0xffffffffu, v, 8);
        v += __shfl_xor_sync(0xffffffffu, v, 4);
        v += __shfl_xor_sync(0xffffffffu, v, 2);
        v += __shfl_xor_sync(0xffffffffu, v, 1);
        bv[i] = v;
    }
    float muPmu = 0.0f;
#pragma unroll
    for (int i = 0; i < 16; ++i) muPmu += bv[i] * mu[w * 16 + i];

    if (lane < 16) {
#pragma unroll
        for (int i = 0; i < 16; ++i) {
            if (i <= j) {
                float c = (i == j ? -0.5f : -1.0f) * inv[i];
                g_all[(j * (j + 1) / 2 + i) * KC + w] = c;
            }
        }
    }
    if (lane == 0) {
#pragma unroll
        for (int i = 0; i < 16; ++i) g_all[(NQUAD + i) * KC + w] = bv[i];
        g_all[NFEAT * KC + w] =
            logf(pi[w]) - 0.5f * logdet - 8.0f * 1.8378770664093453f - 0.5f * muPmu;
    }
}

// ---------------------------------------------------------------------------
// Main kernel: ONE point per thread. X scalar (16 regs), acc packs 2 clusters
// per f32x2 (16 regs). Per feature: 1 FMUL (scalar product) + 1 ALU dup-mov +
// 8 f2fma with constant-bank (uniform-path) coefficients. Half the registers
// of the 2pt/thread variant -> 5 CTAs/SM (~60% occ) to hide latency and push
// the FMA pipe toward saturation. Epilogue uses MUFU __expf (pipe is idle).
// ---------------------------------------------------------------------------
__global__ void __launch_bounds__(256, 5) gmm_main(const float* __restrict__ x,
                                                   float* __restrict__ out, int n) {
    long long t = (long long)blockIdx.x * blockDim.x + threadIdx.x;
    if (t >= n) return;

    const float4* x4 = reinterpret_cast<const float4*>(x + t * DD);
    float X[16];
#pragma unroll
    for (int q = 0; q < 4; ++q) {
        float4 v = x4[q];
        X[4 * q + 0] = v.x; X[4 * q + 1] = v.y; X[4 * q + 2] = v.z; X[4 * q + 3] = v.w;
    }

    const ulonglong2* cvec = reinterpret_cast<const ulonglong2*>(c_all);

    unsigned long long acc[8];
#pragma unroll
    for (int m = 0; m < 4; ++m) {
        ulonglong2 c = cvec[NFEAT * 4 + m];   // constants row
        acc[2 * m] = c.x; acc[2 * m + 1] = c.y;
    }

    // quadratic features (i<=j), feature p = j*(j+1)/2 + i
    int p = 0;
#pragma unroll
    for (int j = 0; j < 16; ++j) {
#pragma unroll
        for (int i = 0; i <= j; ++i) {
            unsigned long long f = f2dup(X[i] * X[j]);
#pragma unroll
            for (int m = 0; m < 4; ++m) {
                ulonglong2 cc = cvec[p * 4 + m];      // clusters 4m..4m+3
                acc[2 * m]     = f2fma(cc.x, f, acc[2 * m]);
                acc[2 * m + 1] = f2fma(cc.y, f, acc[2 * m + 1]);
            }
            ++p;
        }
    }
    // linear features
#pragma unroll
    for (int i = 0; i < 16; ++i) {
        unsigned long long f = f2dup(X[i]);
#pragma unroll
        for (int m = 0; m < 4; ++m) {
            ulonglong2 cc = cvec[(NQUAD + i) * 4 + m];
            acc[2 * m]     = f2fma(cc.x, f, acc[2 * m]);
            acc[2 * m + 1] = f2fma(cc.y, f, acc[2 * m + 1]);
        }
    }

    // unpack logits (reuse X storage)
    float l[16];
#pragma unroll
    for (int m = 0; m < 8; ++m) f2unpack(acc[m], l[2 * m], l[2 * m + 1]);

    // softmax + store
    float mx = l[0];
#pragma unroll
    for (int k = 1; k < 16; ++k) mx = fmaxf(mx, l[k]);
    float e[16], s = 0.0f;
#pragma unroll
    for (int k = 0; k < 16; ++k) { e[k] = __expf(l[k] - mx); s += e[k]; }
    float r = __fdividef(1.0f, s);
    float4* o = reinterpret_cast<float4*>(out + t * KC);
    o[0] = make_float4(e[0] * r,  e[1] * r,  e[2] * r,  e[3] * r);
    o[1] = make_float4(e[4] * r,  e[5] * r,  e[6] * r,  e[7] * r);
    o[2] = make_float4(e[8] * r,  e[9] * r,  e[10] * r, e[11] * r);
    o[3] = make_float4(e[12] * r, e[13] * r, e[14] * r, e[15] * r);
}

extern "C" void kernel_launch(void* const* d_in, const int* in_sizes, int n_in,
                              void* d_out, int out_size) {
    const float* x     = (const float*)d_in[0];
    const float* pi    = (const float*)d_in[1];
    const float* mu    = (const float*)d_in[2];
    const float* Sigma = (const float*)d_in[3];
    float* out = (float*)d_out;

    int n = in_sizes[0] / DD;

    gmm_precompute<<<1, 512>>>(pi, mu, Sigma);

    void* gall_addr = nullptr;
    cudaGetSymbolAddress(&gall_addr, g_all);
    cudaMemcpyToSymbolAsync(c_all, gall_addr, sizeof(float) * NALL * KC, 0,
                            cudaMemcpyDeviceToDevice, 0);

    int block = 256;
    int grid  = (n + block - 1) / block;
    gmm_main<<<grid, block>>>(x, out, n);
}